// round 6
// baseline (speedup 1.0000x reference)
#include <cuda_runtime.h>
#include <cuda_fp16.h>
#include <cstdint>

// ---------------------------------------------------------------------------
// GPe masked GEMM: out[b,u] = sum_i inputs[b,i]*(w[i,u]*mask[u,i]) + bias[u]
// compute_103 (no 'a') -> legacy mma.sync.m16n8k16 fp16/f32acc path.
// R6: 2 CTAs/SM. 128x128x64 CTA tile, warp tile 64x32, 3-stage cp.async ring
// (96KB smem/CTA), <=128 regs/thread, ldmatrix.x4 fragments.
// ---------------------------------------------------------------------------

#define DB 16384
#define DK 3072
#define DN 3072
#define BM 128
#define BN 128
#define BK 64
#define NKI (DK / BK)          /* 48 */
#define NSTG 3
#define ROWB 128                              /* bytes per smem row (64 fp16) */
#define A_STAGE_BYTES (BM * ROWB)             /* 16384 */
#define B_STAGE_BYTES (BN * ROWB)             /* 16384 */
#define STAGE_BYTES (A_STAGE_BYTES + B_STAGE_BYTES)  /* 32768 */
#define SMEM_BYTES (NSTG * STAGE_BYTES)              /* 98304 */

#define W_SCALE 16384.0f
#define W_INV   (1.0f / 16384.0f)

__device__ __align__(128) __half g_Ah[(size_t)DB * DK];  // fp16 inputs
__device__ __align__(128) __half g_Wh[(size_t)DN * DK];  // fp16 (w*mask*2^14)^T, [N,K]

// ------------------------------- helpers -----------------------------------

__device__ __forceinline__ void cp16(uint32_t d, const void* s) {
    asm volatile("cp.async.cg.shared.global [%0], [%1], 16;" :: "r"(d), "l"(s) : "memory");
}
__device__ __forceinline__ void cp_commit() { asm volatile("cp.async.commit_group;" ::: "memory"); }
template <int N>
__device__ __forceinline__ void cp_wait() { asm volatile("cp.async.wait_group %0;" :: "n"(N) : "memory"); }

__device__ __forceinline__ void ldsm4(uint32_t& r0, uint32_t& r1, uint32_t& r2, uint32_t& r3,
                                      uint32_t addr) {
    asm volatile("ldmatrix.sync.aligned.m8n8.x4.shared.b16 {%0,%1,%2,%3}, [%4];"
                 : "=r"(r0), "=r"(r1), "=r"(r2), "=r"(r3) : "r"(addr));
}

__device__ __forceinline__ void mma_f16(float& d0, float& d1, float& d2, float& d3,
                                        uint32_t a0, uint32_t a1, uint32_t a2, uint32_t a3,
                                        uint32_t b0, uint32_t b1) {
    asm volatile("mma.sync.aligned.m16n8k16.row.col.f32.f16.f16.f32 "
                 "{%0,%1,%2,%3}, {%4,%5,%6,%7}, {%8,%9}, {%0,%1,%2,%3};"
                 : "+f"(d0), "+f"(d1), "+f"(d2), "+f"(d3)
                 : "r"(a0), "r"(a1), "r"(a2), "r"(a3), "r"(b0), "r"(b1));
}

// --------------------------- prep kernels ----------------------------------

__global__ void prep_a_kernel(const float4* __restrict__ in) {
    size_t i = (size_t)blockIdx.x * blockDim.x + threadIdx.x;
    const size_t stride = (size_t)gridDim.x * blockDim.x;
    uint2* o = reinterpret_cast<uint2*>(g_Ah);
    const size_t n4 = (size_t)DB * DK / 4;
    for (; i < n4; i += stride) {
        float4 v = __ldg(in + i);
        __half2 h01 = __floats2half2_rn(v.x, v.y);
        __half2 h23 = __floats2half2_rn(v.z, v.w);
        uint2 u;
        u.x = *reinterpret_cast<uint32_t*>(&h01);
        u.y = *reinterpret_cast<uint32_t*>(&h23);
        o[i] = u;
    }
}

// g_Wh[n][k] = half(w[k][n] * mask[n][k] * 2^14), 32x32 smem transpose tiles.
__global__ void prep_w_kernel(const float* __restrict__ w, const int* __restrict__ mask) {
    __shared__ float t[32][33];
    const int k0 = blockIdx.x * 32, n0 = blockIdx.y * 32;
    const int tx = threadIdx.x, ty = threadIdx.y;   // (32, 8)
#pragma unroll
    for (int j = 0; j < 4; ++j) {
        int k = k0 + ty + 8 * j;
        t[ty + 8 * j][tx] = w[(size_t)k * DN + n0 + tx];
    }
    __syncthreads();
#pragma unroll
    for (int j = 0; j < 4; ++j) {
        int n = n0 + ty + 8 * j;
        int k = k0 + tx;
        float v = t[tx][ty + 8 * j] * (float)mask[(size_t)n * DK + k] * W_SCALE;
        g_Wh[(size_t)n * DK + k] = __float2half_rn(v);
    }
}

// ------------------------------ GEMM ---------------------------------------
// Smem stage: A[128 rows][128B] then B[128 rows][128B]. 16B-chunk xor swizzle
// within a row: chunk' = chunk ^ (row & 7). Conflict-free for cp.async writes
// and ldmatrix reads.

__global__ void __launch_bounds__(256, 2) gemm_f16(const float* __restrict__ bias,
                                                   float* __restrict__ out) {
    extern __shared__ char smem[];

    const int tid = threadIdx.x;
    const int wid = tid >> 5;
    const int lane = tid & 31;
    const int gid = lane >> 2;
    const int tg = lane & 3;
    const int warp_m = wid & 1;     // 64-row slice
    const int warp_n = wid >> 1;    // 32-col slice (0..3)
    const int m0 = blockIdx.y * BM;
    const int n0 = blockIdx.x * BN;

    const uint32_t smemBase = (uint32_t)__cvta_generic_to_shared(smem);

    // ---- cp.async base mapping (linear in chunk-group j) -------------------
    // row = (tid>>3) + 32*j, c4 = tid&7, key = row&7 invariant in j.
    const int r0 = tid >> 3;
    const int c4 = tid & 7;
    const uint32_t key0 = (uint32_t)(r0 & 7);
    const uint32_t dstRow0 = (uint32_t)r0 * ROWB + (((uint32_t)c4 ^ key0) << 4);
    const char* aSrc0 = (const char*)(g_Ah + (size_t)(m0 + r0) * DK + c4 * 8);
    const char* bSrc0 = (const char*)(g_Wh + (size_t)(n0 + r0) * DK + c4 * 8);
    const size_t srcRowStride = (size_t)32 * DK * 2;   // 32 rows down per j

    // ---- ldmatrix row bases ------------------------------------------------
    const int ac0 = lane >> 4;                          // A chunk base
    const int arow = warp_m * 64 + (lane & 15);
    const int bc0 = (lane >> 3) & 1;                    // B chunk base
    const int brow = warp_n * 32 + ((lane >> 4) << 3) + (lane & 7);

    uint32_t aBase[4], aKey[4], bBase[2], bKey[2];
#pragma unroll
    for (int mi = 0; mi < 4; ++mi) {
        int row = arow + mi * 16;
        aBase[mi] = (uint32_t)row * ROWB;
        aKey[mi] = (uint32_t)(row & 7);
    }
#pragma unroll
    for (int nj = 0; nj < 2; ++nj) {
        int row = brow + nj * 16;
        bBase[nj] = A_STAGE_BYTES + (uint32_t)row * ROWB;
        bKey[nj] = (uint32_t)(row & 7);
    }

    float acc[4][4][4];
#pragma unroll
    for (int mi = 0; mi < 4; ++mi)
#pragma unroll
        for (int ni = 0; ni < 4; ++ni)
#pragma unroll
            for (int q = 0; q < 4; ++q) acc[mi][ni][q] = 0.0f;

    // ---- prologue: fill stages 0..NSTG-2 -----------------------------------
#pragma unroll
    for (int p = 0; p < NSTG - 1; ++p) {
        uint32_t st = smemBase + p * STAGE_BYTES;
        size_t kofs = (size_t)p * (BK * 2);
#pragma unroll
        for (int j = 0; j < 4; ++j)
            cp16(st + dstRow0 + j * 32 * ROWB, aSrc0 + j * srcRowStride + kofs);
#pragma unroll
        for (int j = 0; j < 4; ++j)
            cp16(st + A_STAGE_BYTES + dstRow0 + j * 32 * ROWB, bSrc0 + j * srcRowStride + kofs);
        cp_commit();
    }

    // ---- mainloop (rolling stage indices, NSTG=3) --------------------------
    int cpSt = 0;                 // stage being computed
    int ldSt = NSTG - 1;          // stage being filled
    for (int it = 0; it < NKI; ++it) {
        cp_wait<NSTG - 2>();
        __syncthreads();

        const int nf = it + NSTG - 1;
        if (nf < NKI) {
            uint32_t st = smemBase + ldSt * STAGE_BYTES;
            size_t kofs = (size_t)nf * (BK * 2);
#pragma unroll
            for (int j = 0; j < 4; ++j)
                cp16(st + dstRow0 + j * 32 * ROWB, aSrc0 + j * srcRowStride + kofs);
#pragma unroll
            for (int j = 0; j < 4; ++j)
                cp16(st + A_STAGE_BYTES + dstRow0 + j * 32 * ROWB, bSrc0 + j * srcRowStride + kofs);
        }
        cp_commit();

        const uint32_t stg = smemBase + cpSt * STAGE_BYTES;
#pragma unroll
        for (int ks = 0; ks < 4; ++ks) {
            uint32_t bf[2][4];
#pragma unroll
            for (int nj = 0; nj < 2; ++nj)
                ldsm4(bf[nj][0], bf[nj][1], bf[nj][2], bf[nj][3],
                      stg + bBase[nj] + ((((uint32_t)(bc0 + 2 * ks)) ^ bKey[nj]) << 4));
#pragma unroll
            for (int mi = 0; mi < 4; ++mi) {
                uint32_t a0, a1, a2, a3;
                ldsm4(a0, a1, a2, a3,
                      stg + aBase[mi] + ((((uint32_t)(ac0 + 2 * ks)) ^ aKey[mi]) << 4));
#pragma unroll
                for (int nj = 0; nj < 2; ++nj) {
                    mma_f16(acc[mi][2 * nj][0], acc[mi][2 * nj][1],
                            acc[mi][2 * nj][2], acc[mi][2 * nj][3],
                            a0, a1, a2, a3, bf[nj][0], bf[nj][1]);
                    mma_f16(acc[mi][2 * nj + 1][0], acc[mi][2 * nj + 1][1],
                            acc[mi][2 * nj + 1][2], acc[mi][2 * nj + 1][3],
                            a0, a1, a2, a3, bf[nj][2], bf[nj][3]);
                }
            }
        }
        cpSt = (cpSt + 1 == NSTG) ? 0 : cpSt + 1;
        ldSt = (ldSt + 1 == NSTG) ? 0 : ldSt + 1;
    }
    cp_wait<0>();

    // ---- epilogue: scale 2^-14 + bias, float2 direct stores ----------------
#pragma unroll
    for (int mi = 0; mi < 4; ++mi) {
        const int row0 = m0 + warp_m * 64 + mi * 16 + gid;
#pragma unroll
        for (int ni = 0; ni < 4; ++ni) {
            const int col = n0 + warp_n * 32 + ni * 8 + 2 * tg;
            const float2 bb = *reinterpret_cast<const float2*>(bias + col);
            float2 v0, v1;
            v0.x = acc[mi][ni][0] * W_INV + bb.x;
            v0.y = acc[mi][ni][1] * W_INV + bb.y;
            v1.x = acc[mi][ni][2] * W_INV + bb.x;
            v1.y = acc[mi][ni][3] * W_INV + bb.y;
            *reinterpret_cast<float2*>(out + (size_t)row0 * DN + col) = v0;
            *reinterpret_cast<float2*>(out + (size_t)(row0 + 8) * DN + col) = v1;
        }
    }
}

// ------------------------------ launch -------------------------------------

extern "C" void kernel_launch(void* const* d_in, const int* in_sizes, int n_in,
                              void* d_out, int out_size) {
    (void)in_sizes; (void)n_in; (void)out_size;
    const float* inp  = (const float*)d_in[0];
    const float* w    = (const float*)d_in[1];
    const float* bias = (const float*)d_in[2];
    const int*   mask = (const int*)d_in[3];
    float* out = (float*)d_out;

    static bool attr_set = false;
    if (!attr_set) {
        cudaFuncSetAttribute(gemm_f16, cudaFuncAttributeMaxDynamicSharedMemorySize, SMEM_BYTES);
        attr_set = true;
    }

    prep_a_kernel<<<4096, 256>>>((const float4*)inp);
    prep_w_kernel<<<dim3(DK / 32, DN / 32), dim3(32, 8)>>>(w, mask);
    gemm_f16<<<dim3(DN / BN, DB / BM), 256, SMEM_BYTES>>>(bias, out);
}